// round 15
// baseline (speedup 1.0000x reference)
#include <cuda_runtime.h>
#include <cuda_bf16.h>
#include <cmath>
#include <cstdint>

// ---------------- problem dims ----------------
#define BATCH   8192
#define D_IN    512
#define D_HID   256
#define D_OUT   128

#define GTILE   128
#define NCHUNK  4

// sqrt(log2(e)): Zhi scaled by this => gram accumulators are log2-domain
#define ZSCALE  1.2011224087864498f
#define LN2F    0.6931471805599453f

// ---------------- device scratch ----------------
__device__ __align__(16) __nv_bfloat16 g_xhi[3][BATCH * D_IN];
__device__ __align__(16) __nv_bfloat16 g_xlo[3][BATCH * D_IN];
__device__ __align__(16) __nv_bfloat16 g_W1t_hi[3][D_HID * D_IN];
__device__ __align__(16) __nv_bfloat16 g_W1t_lo[3][D_HID * D_IN];
__device__ __align__(16) __nv_bfloat16 g_W2t_hi[3][D_OUT * D_HID];
__device__ __align__(16) __nv_bfloat16 g_W2t_lo[3][D_OUT * D_HID];
__device__ float g_Y[3][BATCH * D_OUT];
__device__ __align__(16) __nv_bfloat16 g_Zhi[3][BATCH * D_OUT];
__device__ float g_psum[3][128][D_OUT];
__device__ float g_psq[3][128][D_OUT];
__device__ float g_mean[3][D_OUT];
__device__ float g_sd[3][D_OUT];
__device__ float g_rspart[5][NCHUNK][BATCH];   // row partials (chunk slots)
__device__ float g_colpart[2][64][BATCH];      // sym-gram col partials (slot = source i-tile)
__device__ float g_pos[3][BATCH];
__device__ double g_lpart[64];

// gram configs: 0:BB 1:EE 2:BE 3:BF 4:EF
__constant__ int c_ga[5]   = {0, 1, 0, 0, 1};
__constant__ int c_gb[5]   = {0, 1, 1, 2, 2};
__constant__ int c_same[5] = {1, 1, 0, 0, 0};

// ---------------- PTX helpers (sm_80-level only) ----------------
__device__ __forceinline__ uint32_t smem_u32(const void* p) {
    return (uint32_t)__cvta_generic_to_shared(p);
}
__device__ __forceinline__ void cp16(uint32_t dst, const void* src) {
    asm volatile("cp.async.cg.shared.global [%0], [%1], 16;"
                 :: "r"(dst), "l"(__cvta_generic_to_global(src)) : "memory");
}
__device__ __forceinline__ void cp_commit() {
    asm volatile("cp.async.commit_group;" ::: "memory");
}
__device__ __forceinline__ void cp_wait0() {
    asm volatile("cp.async.wait_group 0;" ::: "memory");
}

#define LDSM_X4(r, addr) \
    asm volatile("ldmatrix.sync.aligned.m8n8.x4.shared.b16 {%0,%1,%2,%3}, [%4];" \
        : "=r"((r)[0]), "=r"((r)[1]), "=r"((r)[2]), "=r"((r)[3]) : "r"(addr))

#define MMA16816(d, a, b0, b1) \
    asm volatile("mma.sync.aligned.m16n8k16.row.col.f32.bf16.bf16.f32 " \
        "{%0,%1,%2,%3}, {%4,%5,%6,%7}, {%8,%9}, {%0,%1,%2,%3};" \
        : "+f"((d)[0]), "+f"((d)[1]), "+f"((d)[2]), "+f"((d)[3]) \
        : "r"((a)[0]), "r"((a)[1]), "r"((a)[2]), "r"((a)[3]), "r"(b0), "r"(b1))

__device__ __forceinline__ void bsplit(float v, __nv_bfloat16& hi, __nv_bfloat16& lo) {
    hi = __float2bfloat16(v);
    lo = __float2bfloat16(v - __bfloat162float(hi));
}

// MUFU 2^x
__device__ __forceinline__ float ex2(float x) {
    float y;
    asm("ex2.approx.f32 %0, %1;" : "=f"(y) : "f"(x));
    return y;
}
// FMA-pipe 2^x via e^(x ln2), |x| <= ~1.52 -> |t| <= 1.06
__device__ __forceinline__ float tex2(float x) {
    float t = x * LN2F;
    float r = 2.48015873e-5f;
    r = fmaf(r, t, 1.98412698e-4f);
    r = fmaf(r, t, 1.38888889e-3f);
    r = fmaf(r, t, 8.33333333e-3f);
    r = fmaf(r, t, 4.16666667e-2f);
    r = fmaf(r, t, 1.66666667e-1f);
    r = fmaf(r, t, 0.5f);
    r = fmaf(r, t, 1.0f);
    r = fmaf(r, t, 1.0f);
    return r;
}

// ---------------- smem tile geometry ----------------
#define TPITCH     272
#define TILE_BYTES (128 * TPITCH)           // 34816
#define TP64       144
#define T64B       (128 * TP64)             // 18432 (128-row k64 tile)
#define T64R64     (64 * TP64)              // 9216  (64-row k64 tile)

__device__ __forceinline__ void load_tile(uint32_t dst, const __nv_bfloat16* src,
                                          int strideElems, int tid) {
    #pragma unroll
    for (int idx = tid; idx < 2048; idx += 256) {
        int r = idx >> 4, c = idx & 15;
        cp16(dst + r * TPITCH + c * 16, src + r * strideElems + c * 8);
    }
}
__device__ __forceinline__ void load_tile64(uint32_t dst, const __nv_bfloat16* src,
                                            int strideElems, int tid) {
    #pragma unroll
    for (int idx = tid; idx < 1024; idx += 256) {
        int r = idx >> 3, c = idx & 7;
        cp16(dst + r * TP64 + c * 16, src + r * strideElems + c * 8);
    }
}
__device__ __forceinline__ void load_t64r64(uint32_t dst, const __nv_bfloat16* src,
                                            int strideElems, int tid) {
    #pragma unroll
    for (int idx = tid; idx < 512; idx += 256) {
        int r = idx >> 3, c = idx & 7;
        cp16(dst + r * TP64 + c * 16, src + r * strideElems + c * 8);
    }
}

// K=128 mma pass (gram): acc[4][4][4], warp tile 64x32
__device__ __forceinline__ void mma_pass(float acc[4][4][4], uint32_t aBase, uint32_t bBase) {
    #pragma unroll
    for (int ks = 0; ks < 8; ks++) {
        const uint32_t kb = (uint32_t)ks * 32;
        uint32_t a[4][4], b[2][4];
        #pragma unroll
        for (int mf = 0; mf < 4; mf++)
            LDSM_X4(a[mf], aBase + (uint32_t)(mf * 16) * TPITCH + kb);
        #pragma unroll
        for (int ng = 0; ng < 2; ng++)
            LDSM_X4(b[ng], bBase + (uint32_t)(ng * 16) * TPITCH + kb);
        #pragma unroll
        for (int mf = 0; mf < 4; mf++) {
            #pragma unroll
            for (int nf = 0; nf < 4; nf++) {
                const int ng = nf >> 1, od = nf & 1;
                MMA16816(acc[mf][nf], a[mf], b[ng][od], b[ng][od + 2]);
            }
        }
    }
}
// K=64 mma pass, warp tile 32x32 (mf=2): acc[2][4][4]
__device__ __forceinline__ void mma_pass64_m2(float acc[2][4][4], uint32_t aBase, uint32_t bBase) {
    #pragma unroll
    for (int ks = 0; ks < 4; ks++) {
        const uint32_t kb = (uint32_t)ks * 32;
        uint32_t a[2][4], b[2][4];
        #pragma unroll
        for (int mf = 0; mf < 2; mf++)
            LDSM_X4(a[mf], aBase + (uint32_t)(mf * 16) * TP64 + kb);
        #pragma unroll
        for (int ng = 0; ng < 2; ng++)
            LDSM_X4(b[ng], bBase + (uint32_t)(ng * 16) * TP64 + kb);
        #pragma unroll
        for (int mf = 0; mf < 2; mf++) {
            #pragma unroll
            for (int nf = 0; nf < 4; nf++) {
                const int ng = nf >> 1, od = nf & 1;
                MMA16816(acc[mf][nf], a[mf], b[ng][od], b[ng][od + 2]);
            }
        }
    }
}

// ---------------- stage 0: all bf16 hi/lo splits in one launch ----------------
struct WArgs { const float* W1[3]; const float* W2[3]; };
#define NXF4   (BATCH * D_IN / 4)            // 1048576 float4 slots
#define NW1    (D_IN * D_HID)                // 131072
#define NW2    (D_HID * D_OUT)               // 32768
#define SPLIT_BLOCKS ((NXF4 + NW1 + NW2) / 256)  // 4736

__global__ void split_all(const float* xB, const float* xE, const float* xF, WArgs wa) {
    int h = blockIdx.y;
    int idx = blockIdx.x * 256 + threadIdx.x;
    if (idx < NXF4) {
        const float* x = (h == 0) ? xB : ((h == 1) ? xE : xF);
        int base = idx * 4;
        float4 v = *(const float4*)(x + base);
        __nv_bfloat16 h0, h1, h2, h3, l0, l1, l2, l3;
        bsplit(v.x, h0, l0); bsplit(v.y, h1, l1);
        bsplit(v.z, h2, l2); bsplit(v.w, h3, l3);
        __nv_bfloat162* dh = (__nv_bfloat162*)(g_xhi[h] + base);
        __nv_bfloat162* dl = (__nv_bfloat162*)(g_xlo[h] + base);
        dh[0] = __nv_bfloat162(h0, h1); dh[1] = __nv_bfloat162(h2, h3);
        dl[0] = __nv_bfloat162(l0, l1); dl[1] = __nv_bfloat162(l2, l3);
    } else if (idx < NXF4 + NW1) {
        int widx = idx - NXF4;
        int k = widx >> 8, n = widx & 255;
        __nv_bfloat16 hi, lo;
        bsplit(wa.W1[h][widx], hi, lo);
        g_W1t_hi[h][n * D_IN + k] = hi;
        g_W1t_lo[h][n * D_IN + k] = lo;
    } else {
        int i2 = idx - NXF4 - NW1;
        int k = i2 >> 7, n = i2 & 127;
        __nv_bfloat16 hi, lo;
        bsplit(wa.W2[h][i2], hi, lo);
        g_W2t_hi[h][n * D_HID + k] = hi;
        g_W2t_lo[h][n * D_HID + k] = lo;
    }
}

// ---------------- stage 1: fully fused MLP (H stays in smem) ----------------
struct BArgs { const float* b1[3]; const float* b2[3]; };

// smem layout: H region (8 x 64-row k64 tiles: hi 0..3, lo 4..7) then 2 load buffers
#define HBASE      0
#define HTILE(kt)  ((uint32_t)(HBASE + (kt) * T64R64))
#define FBUF(b)    ((uint32_t)(8 * T64R64 + (b) * 55296))
#define FB_XHI     0
#define FB_XLO     T64R64
#define FB_WHI     (2 * T64R64)
#define FB_WLO     (2 * T64R64 + T64B)
#define FUSED_SMEM (8 * T64R64 + 2 * 55296)   // 73728 + 110592 = 184320

// grid (128, 1, 3): 64 rows per CTA. 256 threads, warp grid 2x4, warp tile 32x32.
__global__ __launch_bounds__(256, 1) void mlp_fused(BArgs ba) {
    extern __shared__ unsigned char smem[];
    __shared__ float scs[D_OUT][2];
    __shared__ float scq[D_OUT][2];
    uint32_t sb = smem_u32(smem);
    const int tid = threadIdx.x, lane = tid & 31, w = tid >> 5;
    const int wr = w >> 2, wc = w & 3, group = lane >> 2, tig = lane & 3;
    const int h = blockIdx.z;
    const int iBase = blockIdx.x * 64;

    const __nv_bfloat16* Xhi = g_xhi[h];
    const __nv_bfloat16* Xlo = g_xlo[h];
    const __nv_bfloat16* W1hi = g_W1t_hi[h];
    const __nv_bfloat16* W1lo = g_W1t_lo[h];
    const __nv_bfloat16* W2hi = g_W2t_hi[h];
    const __nv_bfloat16* W2lo = g_W2t_lo[h];
    const float* __restrict__ b1 = ba.b1[h];
    const float* __restrict__ b2 = ba.b2[h];

    const uint32_t rowSel = (uint32_t)(lane & 15) * TP64;
    const uint32_t colSel = (uint32_t)((lane >> 4) << 4);
    const uint32_t aOff = (uint32_t)(wr * 32) * TP64 + rowSel + colSel;
    const uint32_t bOff = (uint32_t)(wc * 32) * TP64 + rowSel + colSel;

    float acc[2][4][4];
    #pragma unroll
    for (int mf = 0; mf < 2; mf++)
        #pragma unroll
        for (int nf = 0; nf < 4; nf++)
            #pragma unroll
            for (int e = 0; e < 4; e++) acc[mf][nf][e] = 0.0f;

    // ---- phase 1: H = relu(x @ W1 + b1), two n-halves, 8 k64 chunks each ----
    load_t64r64(FBUF(0) + FB_XHI + sb, Xhi + (size_t)iBase * D_IN, D_IN, tid);
    load_t64r64(FBUF(0) + FB_XLO + sb, Xlo + (size_t)iBase * D_IN, D_IN, tid);
    load_tile64(FBUF(0) + FB_WHI + sb, W1hi, D_IN, tid);
    load_tile64(FBUF(0) + FB_WLO + sb, W1lo, D_IN, tid);
    cp_commit();

    for (int step = 0; step < 16; step++) {
        const int buf = step & 1;
        const int nh = step >> 3;
        cp_wait0();
        __syncthreads();
        if (step < 15) {
            const int s1 = step + 1;
            const int nh1 = s1 >> 3, kc1 = s1 & 7;
            load_t64r64(FBUF(buf ^ 1) + FB_XHI + sb, Xhi + (size_t)iBase * D_IN + kc1 * 64, D_IN, tid);
            load_t64r64(FBUF(buf ^ 1) + FB_XLO + sb, Xlo + (size_t)iBase * D_IN + kc1 * 64, D_IN, tid);
            load_tile64(FBUF(buf ^ 1) + FB_WHI + sb, W1hi + (size_t)(nh1 * 128) * D_IN + kc1 * 64, D_IN, tid);
            load_tile64(FBUF(buf ^ 1) + FB_WLO + sb, W1lo + (size_t)(nh1 * 128) * D_IN + kc1 * 64, D_IN, tid);
            cp_commit();
        }
        const uint32_t xh = sb + FBUF(buf) + FB_XHI + aOff;
        const uint32_t xl = sb + FBUF(buf) + FB_XLO + aOff;
        const uint32_t wh = sb + FBUF(buf) + FB_WHI + bOff;
        const uint32_t wl = sb + FBUF(buf) + FB_WLO + bOff;
        mma_pass64_m2(acc, xh, wh);
        mma_pass64_m2(acc, xh, wl);
        mma_pass64_m2(acc, xl, wh);

        if ((step & 7) == 7) {
            // half epilogue: bias + relu + bsplit -> smem H tiles
            #pragma unroll
            for (int mf = 0; mf < 2; mf++) {
                const int r = wr * 32 + mf * 16 + group;
                #pragma unroll
                for (int nf = 0; nf < 4; nf++) {
                    const int cl = wc * 32 + nf * 8 + tig * 2;
                    const int cg = nh * 128 + cl;
                    const float bb0 = b1[cg], bb1 = b1[cg + 1];
                    const int kt = cg >> 6;
                    const uint32_t co = (uint32_t)(cg & 63) * 2;
                    #pragma unroll
                    for (int rr = 0; rr < 2; rr++) {
                        const int rl = r + rr * 8;
                        float v0 = fmaxf(acc[mf][nf][rr * 2 + 0] + bb0, 0.0f);
                        float v1 = fmaxf(acc[mf][nf][rr * 2 + 1] + bb1, 0.0f);
                        __nv_bfloat16 h0, h1, l0, l1;
                        bsplit(v0, h0, l0); bsplit(v1, h1, l1);
                        *(__nv_bfloat162*)(smem + HTILE(kt) + (uint32_t)rl * TP64 + co) =
                            __nv_bfloat162(h0, h1);
                        *(__nv_bfloat162*)(smem + HTILE(4 + kt) + (uint32_t)rl * TP64 + co) =
                            __nv_bfloat162(l0, l1);
                        acc[mf][nf][rr * 2 + 0] = 0.0f;
                        acc[mf][nf][rr * 2 + 1] = 0.0f;
                    }
                }
            }
        }
    }

    // ---- phase 2: Y = H(smem) @ W2 + b2, 4 k64 chunks ----
    __syncthreads();   // all H writes visible; load buffers free
    load_tile64(FBUF(0) + sb, W2hi, D_HID, tid);
    load_tile64(FBUF(0) + T64B + sb, W2lo, D_HID, tid);
    cp_commit();

    for (int kt = 0; kt < 4; kt++) {
        const int buf = kt & 1;
        cp_wait0();
        __syncthreads();
        if (kt < 3) {
            load_tile64(FBUF(buf ^ 1) + sb, W2hi + (kt + 1) * 64, D_HID, tid);
            load_tile64(FBUF(buf ^ 1) + T64B + sb, W2lo + (kt + 1) * 64, D_HID, tid);
            cp_commit();
        }
        const uint32_t hh = sb + HTILE(kt) + aOff;
        const uint32_t hl = sb + HTILE(4 + kt) + aOff;
        const uint32_t wh = sb + FBUF(buf) + bOff;
        const uint32_t wl = sb + FBUF(buf) + T64B + bOff;
        mma_pass64_m2(acc, hh, wh);
        mma_pass64_m2(acc, hh, wl);
        mma_pass64_m2(acc, hl, wh);
    }

    // epilogue: bias + Y write + fused whitening partial sums
    float cs[8] = {0, 0, 0, 0, 0, 0, 0, 0};
    float cq[8] = {0, 0, 0, 0, 0, 0, 0, 0};
    #pragma unroll
    for (int mf = 0; mf < 2; mf++) {
        const int r0 = iBase + wr * 32 + mf * 16 + group;
        #pragma unroll
        for (int nf = 0; nf < 4; nf++) {
            const int c0 = wc * 32 + nf * 8 + tig * 2;
            const float bb0 = b2[c0], bb1 = b2[c0 + 1];
            #pragma unroll
            for (int rr = 0; rr < 2; rr++) {
                const int r = r0 + rr * 8;
                float v0 = acc[mf][nf][rr * 2 + 0] + bb0;
                float v1 = acc[mf][nf][rr * 2 + 1] + bb1;
                *(float2*)(g_Y[h] + (size_t)r * D_OUT + c0) = make_float2(v0, v1);
                cs[nf * 2 + 0] += v0; cq[nf * 2 + 0] = fmaf(v0, v0, cq[nf * 2 + 0]);
                cs[nf * 2 + 1] += v1; cq[nf * 2 + 1] = fmaf(v1, v1, cq[nf * 2 + 1]);
            }
        }
    }
    #pragma unroll
    for (int s = 0; s < 8; s++) {
        #pragma unroll
        for (int off = 4; off <= 16; off <<= 1) {
            cs[s] += __shfl_xor_sync(0xFFFFFFFFu, cs[s], off);
            cq[s] += __shfl_xor_sync(0xFFFFFFFFu, cq[s], off);
        }
    }
    if (group == 0) {
        #pragma unroll
        for (int nf = 0; nf < 4; nf++) {
            #pragma unroll
            for (int e = 0; e < 2; e++) {
                int c = wc * 32 + nf * 8 + tig * 2 + e;
                scs[c][wr] = cs[nf * 2 + e];
                scq[c][wr] = cq[nf * 2 + e];
            }
        }
    }
    __syncthreads();
    if (tid < D_OUT) {
        g_psum[h][blockIdx.x][tid] = scs[tid][0] + scs[tid][1];
        g_psq[h][blockIdx.x][tid]  = scq[tid][0] + scq[tid][1];
    }
}

// ---------------- stage 1b: whitening stats finalize (parallel loads) ----------------
__global__ void stats_final() {
    __shared__ double ssum[8][D_OUT];
    __shared__ double ssq[8][D_OUT];
    int set = blockIdx.x;
    int c = threadIdx.x & 127;
    int part = threadIdx.x >> 7;     // 0..7, 16 row-blocks each
    double s = 0.0, q = 0.0;
    #pragma unroll 4
    for (int b = 0; b < 16; b++) {
        s += (double)g_psum[set][part * 16 + b][c];
        q += (double)g_psq[set][part * 16 + b][c];
    }
    ssum[part][c] = s; ssq[part][c] = q;
    __syncthreads();
    if (part == 0) {
        double S = 0.0, Q = 0.0;
        #pragma unroll
        for (int p = 0; p < 8; p++) { S += ssum[p][c]; Q += ssq[p][c]; }
        double n = (double)BATCH;
        double mean = S / n;
        double var = (Q - S * S / n) / (n - 1.0);
        if (var < 0.0) var = 0.0;
        g_mean[set][c] = (float)mean;
        g_sd[set][c] = (float)(sqrt(var) + 1e-5);
    }
}

// ---------------- stage 1c: fused whiten + L2 normalize + pos dots + scaled bf16 ----------------
__global__ void norm_pos() {
    __shared__ float wss[4][3];
    __shared__ float wpp[4][3];
    int i = blockIdx.x;
    int t = threadIdx.x;
    int wid = t >> 5, lane = t & 31;

    float z[3], ssl[3];
    #pragma unroll
    for (int s = 0; s < 3; s++) {
        float v = (g_Y[s][i * D_OUT + t] - g_mean[s][t]) / g_sd[s][t];
        z[s] = v;
        ssl[s] = v * v;
    }
    #pragma unroll
    for (int s = 0; s < 3; s++)
        #pragma unroll
        for (int o = 16; o > 0; o >>= 1) ssl[s] += __shfl_xor_sync(0xFFFFFFFFu, ssl[s], o);
    if (lane == 0) { wss[wid][0] = ssl[0]; wss[wid][1] = ssl[1]; wss[wid][2] = ssl[2]; }
    __syncthreads();
    #pragma unroll
    for (int s = 0; s < 3; s++) {
        float tot = wss[0][s] + wss[1][s] + wss[2][s] + wss[3][s];
        float nrm = fmaxf(sqrtf(tot), 1e-12f);
        z[s] /= nrm;
    }
    float p[3] = { z[0] * z[1], z[0] * z[2], z[1] * z[2] };
    #pragma unroll
    for (int s = 0; s < 3; s++)
        #pragma unroll
        for (int o = 16; o > 0; o >>= 1) p[s] += __shfl_xor_sync(0xFFFFFFFFu, p[s], o);
    if (lane == 0) { wpp[wid][0] = p[0]; wpp[wid][1] = p[1]; wpp[wid][2] = p[2]; }
    __syncthreads();
    if (t == 0) {
        #pragma unroll
        for (int s = 0; s < 3; s++)
            g_pos[s][i] = wpp[0][s] + wpp[1][s] + wpp[2][s] + wpp[3][s];
    }
    #pragma unroll
    for (int s = 0; s < 3; s++)
        g_Zhi[s][i * D_OUT + t] = __float2bfloat16(z[s] * ZSCALE);
}

// ---------------- stage 2: hi-only bf16 gram, log2-domain, triangle symmetry ----------------
#define SOFF_A    0
#define SOFF_B(b) (TILE_BYTES + (b) * TILE_BYTES)
#define SOFF_RED  (3 * TILE_BYTES)
#define GRAM_SMEM (3 * TILE_BYTES + 2048)   // 106496

__global__ __launch_bounds__(256, 2) void gram_kernel() {
    extern __shared__ unsigned char smem[];
    uint32_t sb = smem_u32(smem);
    float* red = (float*)(smem + SOFF_RED);

    const int tid = threadIdx.x, lane = tid & 31, w = tid >> 5;
    const int wr = w >> 2, wc = w & 3, group = lane >> 2, tig = lane & 3;

    const int g = blockIdx.z;
    const int it = blockIdx.x;
    const int chunk = blockIdx.y;
    const int same = c_same[g];

    if (same && chunk * 16 + 15 < it) return;
    const int jtFirst = same ? max(it, chunk * 16) : chunk * 16;
    const int jtEndEx = chunk * 16 + 16;

    const __nv_bfloat16* __restrict__ A = g_Zhi[c_ga[g]];
    const __nv_bfloat16* __restrict__ B = g_Zhi[c_gb[g]];
    const int iBase = it * GTILE;

    load_tile(sb + SOFF_A, A + (size_t)iBase * D_OUT, D_OUT, tid);
    load_tile(sb + SOFF_B(0), B + (size_t)jtFirst * GTILE * D_OUT, D_OUT, tid);
    cp_commit();

    const uint32_t rowSel = (uint32_t)(lane & 15) * TPITCH;
    const uint32_t colSel = (uint32_t)((lane >> 4) << 4);
    const uint32_t aBase = sb + SOFF_A + (uint32_t)(wr * 64) * TPITCH + rowSel + colSel;
    const uint32_t bOff = (uint32_t)(wc * 32) * TPITCH + rowSel + colSel;

    float rsacc[8] = {0, 0, 0, 0, 0, 0, 0, 0};

    for (int jt = jtFirst; jt < jtEndEx; jt++) {
        const int buf = (jt - jtFirst) & 1;
        const int jBase = jt * GTILE;

        cp_wait0();
        __syncthreads();

        if (jt + 1 < jtEndEx) {
            load_tile(sb + SOFF_B(buf ^ 1), B + (size_t)(jBase + GTILE) * D_OUT, D_OUT, tid);
            cp_commit();
        }

        const uint32_t bBase = sb + SOFF_B(buf) + bOff;

        float acc[4][4][4];
        #pragma unroll
        for (int mf = 0; mf < 4; mf++)
            #pragma unroll
            for (int nf = 0; nf < 4; nf++)
                #pragma unroll
                for (int e = 0; e < 4; e++) acc[mf][nf][e] = 0.0f;

        mma_pass(acc, aBase, bBase);

        if (!same) {
            #pragma unroll
            for (int mf = 0; mf < 4; mf++) {
                float s0 = 0.0f, s1 = 0.0f;
                #pragma unroll
                for (int nf = 0; nf < 4; nf++) {
                    if (mf == 0) {
                        s0 += tex2(acc[mf][nf][0]) + tex2(acc[mf][nf][1]);
                        s1 += tex2(acc[mf][nf][2]) + tex2(acc[mf][nf][3]);
                    } else {
                        s0 += ex2(acc[mf][nf][0]) + ex2(acc[mf][nf][1]);
                        s1 += ex2(acc[mf][nf][2]) + ex2(acc[mf][nf][3]);
                    }
                }
                rsacc[mf * 2 + 0] += s0;
                rsacc[mf * 2 + 1] += s1;
            }
        } else if (jBase == iBase) {
            #pragma unroll
            for (int mf = 0; mf < 4; mf++) {
                const int r0 = wr * 64 + mf * 16 + group;
                float s0 = 0.0f, s1 = 0.0f;
                #pragma unroll
                for (int nf = 0; nf < 4; nf++) {
                    const int c0 = wc * 32 + nf * 8 + tig * 2;
                    #pragma unroll
                    for (int e = 0; e < 4; e++) {
                        const int r = r0 + (e >> 1) * 8;
                        const int c = c0 + (e & 1);
                        float ev = (r == c) ? 1.0f : ex2(acc[mf][nf][e]);
                        if (e < 2) s0 += ev; else s1 += ev;
                    }
                }
                rsacc[mf * 2 + 0] += s0;
                rsacc[mf * 2 + 1] += s1;
            }
        } else {
            float colp[8] = {0, 0, 0, 0, 0, 0, 0, 0};
            #pragma unroll
            for (int mf = 0; mf < 4; mf++) {
                float s0 = 0.0f, s1 = 0.0f;
                #pragma unroll
                for (int nf = 0; nf < 4; nf++) {
                    float e0, e1, e2, e3;
                    if (mf == 0) {
                        e0 = tex2(acc[mf][nf][0]); e1 = tex2(acc[mf][nf][1]);
                        e2 = tex2(acc[mf][nf][2]); e3 = tex2(acc[mf][nf][3]);
                    } else {
                        e0 = ex2(acc[mf][nf][0]); e1 = ex2(acc[mf][nf][1]);
                        e2 = ex2(acc[mf][nf][2]); e3 = ex2(acc[mf][nf][3]);
                    }
                    s0 += e0 + e1;
                    s1 += e2 + e3;
                    colp[nf * 2 + 0] += e0 + e2;
                    colp[nf * 2 + 1] += e1 + e3;
                }
                rsacc[mf * 2 + 0] += s0;
                rsacc[mf * 2 + 1] += s1;
            }
            #pragma unroll
            for (int s = 0; s < 8; s++) {
                #pragma unroll
                for (int off = 4; off <= 16; off <<= 1)
                    colp[s] += __shfl_xor_sync(0xFFFFFFFFu, colp[s], off);
            }
            if (group == 0) {
                #pragma unroll
                for (int nf = 0; nf < 4; nf++) {
                    #pragma unroll
                    for (int e = 0; e < 2; e++) {
                        int c = wc * 32 + nf * 8 + tig * 2 + e;
                        red[c * 2 + wr] = colp[nf * 2 + e];
                    }
                }
            }
            __syncthreads();
            if (tid < 128)
                g_colpart[g][it][jBase + tid] = red[tid * 2] + red[tid * 2 + 1];
        }
    }

    #pragma unroll
    for (int s = 0; s < 8; s++) {
        float v = rsacc[s];
        v += __shfl_xor_sync(0xFFFFFFFFu, v, 1);
        v += __shfl_xor_sync(0xFFFFFFFFu, v, 2);
        rsacc[s] = v;
    }
    __syncthreads();
    if (tig == 0) {
        #pragma unroll
        for (int mf = 0; mf < 4; mf++) {
            #pragma unroll
            for (int e = 0; e < 2; e++) {
                int r = wr * 64 + mf * 16 + group + e * 8;
                red[r * 4 + wc] = rsacc[mf * 2 + e];
            }
        }
    }
    __syncthreads();
    if (tid < 128) {
        float s = red[tid * 4 + 0] + red[tid * 4 + 1] + red[tid * 4 + 2] + red[tid * 4 + 3];
        g_rspart[g][chunk][iBase + tid] = s;
    }
}

// ---------------- stage 3: loss (two-stage, deterministic) ----------------
__global__ void loss_part() {
    __shared__ double sred[128];
    int t = threadIdx.x;
    int i = blockIdx.x * 128 + t;
    int blk = i >> 7;
    int cmin = blk >> 4;

    float rsBB = 0.0f, rsEE = 0.0f;
    for (int c = cmin; c < NCHUNK; c++) {
        rsBB += g_rspart[0][c][i];
        rsEE += g_rspart[1][c][i];
    }
    for (int it2 = 0; it2 < blk; it2++) {
        rsBB += g_colpart[0][it2][i];
        rsEE += g_colpart[1][it2][i];
    }
    float rsBE = 0.0f, rsBF = 0.0f, rsEF = 0.0f;
    #pragma unroll
    for (int c = 0; c < NCHUNK; c++) {
        rsBE += g_rspart[2][c][i];
        rsBF += g_rspart[3][c][i];
        rsEF += g_rspart[4][c][i];
    }
    double acc = 0.0;
    acc += (double)logf(rsBB + rsBE) - (double)g_pos[0][i];
    acc += (double)logf(rsBB + rsBF) - (double)g_pos[1][i];
    acc += (double)logf(rsEE + rsEF) - (double)g_pos[2][i];
    sred[t] = acc;
    __syncthreads();
    for (int s = 64; s > 0; s >>= 1) {
        if (t < s) sred[t] += sred[t + s];
        __syncthreads();
    }
    if (t == 0) g_lpart[blockIdx.x] = sred[0];
}

__global__ void loss_final(float* __restrict__ out) {
    __shared__ double s[64];
    int t = threadIdx.x;
    s[t] = g_lpart[t];
    __syncthreads();
    for (int k = 32; k > 0; k >>= 1) {
        if (t < k) s[t] += s[t + k];
        __syncthreads();
    }
    if (t == 0) out[0] = (float)(s[0] / (3.0 * (double)BATCH));
}

// ---------------- launch ----------------
extern "C" void kernel_launch(void* const* d_in, const int* in_sizes, int n_in,
                              void* d_out, int out_size)
{
    static bool inited = false;
    if (!inited) {
        cudaFuncSetAttribute(gram_kernel, cudaFuncAttributeMaxDynamicSharedMemorySize, GRAM_SMEM);
        cudaFuncSetAttribute(mlp_fused, cudaFuncAttributeMaxDynamicSharedMemorySize, FUSED_SMEM);
        inited = true;
    }

    WArgs wa;
    BArgs ba;
    for (int m = 0; m < 3; m++) {
        wa.W1[m] = (const float*)d_in[3 + 4 * m];
        ba.b1[m] = (const float*)d_in[4 + 4 * m];
        wa.W2[m] = (const float*)d_in[5 + 4 * m];
        ba.b2[m] = (const float*)d_in[6 + 4 * m];
    }

    split_all<<<dim3(SPLIT_BLOCKS, 3), 256>>>(
        (const float*)d_in[0], (const float*)d_in[1], (const float*)d_in[2], wa);

    mlp_fused<<<dim3(BATCH / 64, 1, 3), 256, FUSED_SMEM>>>(ba);

    stats_final<<<3, 1024>>>();
    norm_pos<<<BATCH, 128>>>();

    gram_kernel<<<dim3(BATCH / GTILE, NCHUNK, 5), 256, GRAM_SMEM>>>();

    loss_part<<<64, 128>>>();
    loss_final<<<1, 64>>>((float*)d_out);
}